// round 15
// baseline (speedup 1.0000x reference)
#include <cuda_runtime.h>
#include <cuda_fp16.h>
#include <cstdint>
#include <math.h>

// ---------------------------------------------------------------------------
// Problem constants
// ---------------------------------------------------------------------------
#define Nn 16
#define Hh 112
#define Wd 112
#define Cc 128
#define Ho 110
#define Wo 110
#define Co 256
#define KK 1152                 // 3*3*128
#define MM (Nn*Ho*Wo)           // 193600
#define PIX (Nn*Hh*Wd)          // 200704
#define TT 48400                // winograd tiles: 16*55*55
#define THW 3025                // 55*55
#define NMB 1513                // M-blocks of 32 tiles (48416 padded)
#define FIXCAP (1u << 21)
#define TAU 5e-5f               // |y| threshold for exact fp32 recompute

// ---------------------------------------------------------------------------
// Scratch (device globals; no allocations allowed)
// ---------------------------------------------------------------------------
__device__ float g_s[PIX];
__device__ float g_xni[MM];
__device__ float g_ws[Co];
__device__ float g_ae[Co];
// A image: [stage s=ij*2+half][mblock b][4096B swizzled 32rows x 128B]
__device__ unsigned char g_AtI[32ull * NMB * 4096];
// B image: [stage s][32768B swizzled 256rows x 128B]
__device__ unsigned char g_BtI[32ull * 32768];
__device__ float  g_WT[Co * KK];             // W fp32 [co][k] (fixup)
__device__ uint32_t g_fix_list[FIXCAP];
__device__ uint32_t g_fix_cnt;

__constant__ float c_a0[4] = {1.f, 1.f,  1.f,  0.f};   // A^T row 0
__constant__ float c_a1[4] = {0.f, 1.f, -1.f, -1.f};   // A^T row 1

// ---------------------------------------------------------------------------
// Helpers
// ---------------------------------------------------------------------------
__device__ __forceinline__ uint32_t smem_u32(const void* p) {
    uint32_t a;
    asm("{ .reg .u64 t; cvta.to.shared.u64 t, %1; cvt.u32.u64 %0, t; }"
        : "=r"(a) : "l"(p));
    return a;
}

#define MMA_F16(cc, a, b)                                                     \
    asm volatile("mma.sync.aligned.m16n8k16.row.col.f32.f16.f16.f32 "        \
        "{%0,%1,%2,%3}, {%4,%5,%6,%7}, {%8,%9}, {%0,%1,%2,%3};"              \
        : "+f"((cc)[0]), "+f"((cc)[1]), "+f"((cc)[2]), "+f"((cc)[3])         \
        : "r"((a)[0]), "r"((a)[1]), "r"((a)[2]), "r"((a)[3]),                \
          "r"((b)[0]), "r"((b)[1]))

#define LDSM_X4(r0, r1, r2, r3, addr)                                        \
    asm volatile("ldmatrix.sync.aligned.m8n8.x4.shared.b16 {%0,%1,%2,%3}, [%4];" \
        : "=r"(r0), "=r"(r1), "=r"(r2), "=r"(r3) : "r"(addr))

#define BULK_CP(dst, src, bytes, mbar)                                        \
    asm volatile("cp.async.bulk.shared::cta.global.mbarrier::complete_tx::bytes " \
        "[%0], [%1], %2, [%3];"                                               \
        :: "r"(dst), "l"(src), "r"(bytes), "r"(mbar) : "memory")

#define MBARRIER_INIT(mbar, cnt) \
    asm volatile("mbarrier.init.shared.b64 [%0], %1;" \
                 :: "r"((uint32_t)(mbar)), "r"((uint32_t)(cnt)) : "memory")
#define MBARRIER_EXPECT_TX(mbar, bytes) \
    asm volatile("mbarrier.arrive.expect_tx.shared.b64 _, [%0], %1;" \
                 :: "r"((uint32_t)(mbar)), "r"((uint32_t)(bytes)) : "memory")
#define FENCE_ASYNC() asm volatile("fence.proxy.async.shared::cta;" ::: "memory")

#define MBARRIER_WAIT_PARITY(mbar_addr, phase_parity) do {                       \
    uint32_t _mbar = (uint32_t)(mbar_addr);                                      \
    uint32_t _parity = (uint32_t)(phase_parity);                                 \
    uint32_t _done;                                                              \
    asm volatile("{\n\t.reg .pred p;\n\t"                                        \
        "mbarrier.try_wait.parity.acquire.cta.shared::cta.b64 p, [%1], %2;\n\t"  \
        "selp.b32 %0, 1, 0, p;\n\t}"                                             \
        : "=r"(_done) : "r"(_mbar), "r"(_parity) : "memory");                    \
    if (!_done) {                                                                \
        asm volatile("{\n\t.reg .pred P1;\n\t"                                   \
            "WAIT_LOOP_%=:\n\t"                                                  \
            "mbarrier.try_wait.parity.acquire.cta.shared::cta.b64 P1, [%0], %1, 0x989680;\n\t" \
            "@P1 bra.uni WAIT_DONE_%=;\n\t"                                      \
            "bra.uni WAIT_LOOP_%=;\n\t"                                          \
            "WAIT_DONE_%=:\n\t}"                                                 \
            :: "r"(_mbar), "r"(_parity) : "memory");                             \
    }                                                                            \
} while (0)

// ---------------------------------------------------------------------------
// Kernel 1 (merged): blocks 0..255 = weight norms/exponents (+fix_cnt reset);
// blocks 256..383 = weight transform per input channel; block 384 = A pad.
// ---------------------------------------------------------------------------
__global__ void prep_kernel(const float* __restrict__ W,
                            const float* __restrict__ p,
                            const float* __restrict__ q) {
    int t = threadIdx.x;
    if (blockIdx.x < 256) {
        __shared__ float red[256];
        int c = blockIdx.x;
        if (c == 0 && t == 0) g_fix_cnt = 0;
        float s = 0.0f;
        for (int k = t; k < KK; k += 256) {
            float w = W[k * Co + c];
            s = fmaf(w, w, s);
        }
        red[t] = s; __syncthreads();
        for (int o = 128; o > 0; o >>= 1) {
            if (t < o) red[t] += red[t + o];
            __syncthreads();
        }
        if (t == 0) {
            float qq = q[0] * q[0] * 0.1f;
            g_ws[c] = 1.0f / (sqrtf(red[0]) + qq);
            g_ae[c] = p[c] * p[c] * 0.01f;
        }
        return;
    }
    if (blockIdx.x == 384) {
        for (int i = t; i < 32 * 2048 / 16; i += 256) {
            int s = i / 128;
            int j = (i % 128) * 16;
            *reinterpret_cast<uint4*>(
                g_AtI + ((size_t)s * NMB + (NMB - 1)) * 4096 + 2048 + j) =
                make_uint4(0, 0, 0, 0);
        }
        return;
    }
    int c  = blockIdx.x - 256;          // input channel 0..127
    int co = t;
    float g[3][3];
    #pragma unroll
    for (int r = 0; r < 3; ++r)
        #pragma unroll
        for (int s = 0; s < 3; ++s) {
            float w = W[((r * 3 + s) * Cc + c) * Co + co];
            g[r][s] = w;
            g_WT[(size_t)co * KK + (r * 3 + s) * Cc + c] = w;
        }
    float u[4][3];
    #pragma unroll
    for (int s = 0; s < 3; ++s) {
        u[0][s] = g[0][s];
        u[1][s] = 0.5f * (g[0][s] + g[1][s] + g[2][s]);
        u[2][s] = 0.5f * (g[0][s] - g[1][s] + g[2][s]);
        u[3][s] = g[2][s];
    }
    int half = c >> 6;
    int ch   = (c & 63) >> 3;
    int e    = c & 7;
    uint32_t off = (uint32_t)co * 128u + (uint32_t)((ch ^ (co & 7)) << 4) + e * 2;
    #pragma unroll
    for (int i = 0; i < 4; ++i) {
        float v[4];
        v[0] = u[i][0];
        v[1] = 0.5f * (u[i][0] + u[i][1] + u[i][2]);
        v[2] = 0.5f * (u[i][0] - u[i][1] + u[i][2]);
        v[3] = u[i][2];
        #pragma unroll
        for (int j = 0; j < 4; ++j) {
            int st = (i * 4 + j) * 2 + half;
            *reinterpret_cast<__half*>(g_BtI + (size_t)st * 32768 + off) =
                __float2half_rn(v[j]);
        }
    }
}

// ---------------------------------------------------------------------------
// Kernel 2: Winograd input transform (2 ch/thread) + fused per-pixel sumsq
// via unique tile ownership: pixel (r,c) owned by tile (min(r/2,54),
// min(c/2,54)). Interior tiles own their top-left 2x2; edge tiles own more.
// 64 threads (2 warps) share a tile; reduce 32-lane halves, combine in smem.
// ---------------------------------------------------------------------------
__global__ void in_transform_kernel(const float* __restrict__ x) {
    __shared__ float s_part[4][2][16];   // [tile-in-block][warp-half][pixel]

    int idx = blockIdx.x * 256 + threadIdx.x;    // TT*64 exact
    int tid = threadIdx.x;
    int t  = idx >> 6;
    int cp = idx & 63;
    int c0 = cp * 2;
    int n  = t / THW;
    int rr = t % THW;
    int ty = rr / 55;
    int tx = rr % 55;
    const float* xp = x + (((size_t)n * Hh + 2 * ty) * Wd + 2 * tx) * Cc + c0;

    float da[4][4], db[4][4];
    #pragma unroll
    for (int r = 0; r < 4; ++r)
        #pragma unroll
        for (int s = 0; s < 4; ++s) {
            float2 v = *reinterpret_cast<const float2*>(xp + (r * Wd + s) * Cc);
            da[r][s] = v.x; db[r][s] = v.y;
        }

    // ---- fused sumsq over owned pixels ----
    {
        const int tl    = tid >> 6;          // tile within block (0..3)
        const int whalf = (tid >> 5) & 1;    // which 32-channel half
        const int ndy = (ty == 54) ? 4 : 2;
        const int ndx = (tx == 54) ? 4 : 2;
        #pragma unroll 4
        for (int dy = 0; dy < 4; ++dy) {
            if (dy >= ndy) break;
            #pragma unroll 4
            for (int dx = 0; dx < 4; ++dx) {
                if (dx >= ndx) break;
                float ps = da[dy][dx] * da[dy][dx] + db[dy][dx] * db[dy][dx];
                #pragma unroll
                for (int o = 16; o > 0; o >>= 1)
                    ps += __shfl_xor_sync(0xffffffffu, ps, o);
                if ((tid & 31) == 0) s_part[tl][whalf][dy * 4 + dx] = ps;
            }
        }
        __syncthreads();
        if ((tid & 63) == 0) {     // one thread per tile
            #pragma unroll 4
            for (int dy = 0; dy < 4; ++dy) {
                if (dy >= ndy) break;
                #pragma unroll 4
                for (int dx = 0; dx < 4; ++dx) {
                    if (dx >= ndx) break;
                    g_s[((size_t)n * Hh + 2 * ty + dy) * Wd + 2 * tx + dx] =
                        s_part[tl][0][dy * 4 + dx] + s_part[tl][1][dy * 4 + dx];
                }
            }
        }
    }

    // ---- Winograd transform ----
    float ua[4][4], ub[4][4];
    #pragma unroll
    for (int s = 0; s < 4; ++s) {
        ua[0][s] = da[0][s] - da[2][s];  ub[0][s] = db[0][s] - db[2][s];
        ua[1][s] = da[1][s] + da[2][s];  ub[1][s] = db[1][s] + db[2][s];
        ua[2][s] = da[2][s] - da[1][s];  ub[2][s] = db[2][s] - db[1][s];
        ua[3][s] = da[1][s] - da[3][s];  ub[3][s] = db[1][s] - db[3][s];
    }
    int blk  = t >> 5;
    int row  = t & 31;
    int half = c0 >> 6;
    int ch   = (c0 & 63) >> 3;
    int e    = c0 & 7;        // even
    uint32_t off = (uint32_t)row * 128u + (uint32_t)((ch ^ (row & 7)) << 4) + e * 2;
    #pragma unroll
    for (int i = 0; i < 4; ++i) {
        float va[4], vb[4];
        va[0] = ua[i][0] - ua[i][2];  vb[0] = ub[i][0] - ub[i][2];
        va[1] = ua[i][1] + ua[i][2];  vb[1] = ub[i][1] + ub[i][2];
        va[2] = ua[i][2] - ua[i][1];  vb[2] = ub[i][2] - ub[i][1];
        va[3] = ua[i][1] - ua[i][3];  vb[3] = ub[i][1] - ub[i][3];
        #pragma unroll
        for (int j = 0; j < 4; ++j) {
            int st = (i * 4 + j) * 2 + half;
            *reinterpret_cast<__half2*>(
                g_AtI + ((size_t)st * NMB + blk) * 4096 + off) =
                __halves2half2(__float2half_rn(va[j]), __float2half_rn(vb[j]));
        }
    }
}

// ---------------------------------------------------------------------------
// Kernel 3: 3x3 window sum of g_s -> inverse patch norm
// ---------------------------------------------------------------------------
__global__ void xnorm_kernel(const float* __restrict__ q) {
    int idx = blockIdx.x * 256 + threadIdx.x;
    if (idx >= MM) return;
    int n = idx / (Ho * Wo);
    int r = idx % (Ho * Wo);
    int h = r / Wo;
    int w = r % Wo;
    const float* sp = g_s + ((size_t)n * Hh + h) * Wd + w;
    float sum = 0.0f;
    #pragma unroll
    for (int ky = 0; ky < 3; ++ky)
        sum += sp[ky * Wd] + sp[ky * Wd + 1] + sp[ky * Wd + 2];
    float qq = q[0] * q[0] * 0.1f;
    g_xni[idx] = 1.0f / (sqrtf(sum) + qq);
}

// ---------------------------------------------------------------------------
// Kernel 4 (profiled slot): Winograd GEMM, N-quartered. CTA = 32 tiles x 64
// cout, 128 threads (4 warps x [32t x 16co]), grid (NMB, 4), 4 CTAs/SM.
// Ring-4 bulk-copy pipeline, sync per ij phase. (Unchanged from R14.)
// ---------------------------------------------------------------------------
#define NSTG 32
#define RG_B 4096
#define STG  12288              // A 4KB + B 8KB
#define RING 4
#define SMEM_DYN (RING * STG)   // 49152
#define LISTCAP 8192

extern __shared__ char dsm[];

__global__ void __launch_bounds__(128, 4)
conv_wino_kernel(const float* __restrict__ bias, float* __restrict__ out) {
    __shared__ float s_ws[64], s_ae[64], s_bi[64];
    __shared__ uint32_t s_cnt, s_base;
    __shared__ __align__(8) uint64_t s_mb[RING];

    const uint32_t sbase = smem_u32(dsm);
    const uint32_t mbase = smem_u32(s_mb);
    const int t    = threadIdx.x;
    const int w    = t >> 5;
    const int lane = t & 31;
    const int gid  = lane >> 2;
    const int tig  = lane & 3;
    const int b    = blockIdx.x;
    const int nh   = blockIdx.y;          // N quarter: 0..3
    const int t0   = b * 32;
    const int wno  = w * 16;              // local cout base (0..48)
    const int coB  = nh * 64;             // global cout offset

    if (t < 64) {
        s_ws[t] = g_ws[coB + t];
        s_ae[t] = g_ae[coB + t];
        s_bi[t] = bias[coB + t];
    }
    if (t == 0) {
        s_cnt = 0;
        #pragma unroll
        for (int i = 0; i < RING; ++i) MBARRIER_INIT(mbase + i * 8, 1);
        FENCE_ASYNC();
    }
    __syncthreads();

    // ldmatrix invariants (verified R7-R14)
    const uint32_t sw    = lane & 7;
    const uint32_t aRow0 = (uint32_t)(lane & 15) * 128u;
    const uint32_t aRow1 = aRow0 + 16u * 128u;
    const uint32_t aCsel = (lane >> 4);
    const uint32_t bRow  = (uint32_t)(wno + ((lane >> 4) << 3) + (lane & 7)) * 128u;
    const uint32_t bCsel = (lane >> 3) & 1;

    float O0[16], O1[16], O2[16], O3[16], G[16];
    #pragma unroll
    for (int i = 0; i < 16; ++i) { O0[i]=0.f; O1[i]=0.f; O2[i]=0.f; O3[i]=0.f; G[i]=0.f; }

    #define ISSUE(s) do {                                                     \
        uint32_t buf = sbase + (uint32_t)((s) % RING) * STG;                  \
        uint32_t mb  = mbase + ((s) % RING) * 8;                              \
        MBARRIER_EXPECT_TX(mb, STG);                                          \
        BULK_CP(buf, g_AtI + ((size_t)(s) * NMB + b) * 4096, 4096u, mb);      \
        BULK_CP(buf + RG_B,                                                   \
                g_BtI + (size_t)(s) * 32768 + (size_t)nh * 8192, 8192u, mb);  \
    } while (0)

    #define COMPUTE_STAGE(s) do {                                             \
        MBARRIER_WAIT_PARITY(mbase + ((s) % RING) * 8, ((s) / RING) & 1);     \
        const uint32_t aB = sbase + (uint32_t)((s) % RING) * STG;             \
        const uint32_t bB = aB + RG_B;                                        \
        _Pragma("unroll")                                                     \
        for (int ks = 0; ks < 4; ++ks) {                                      \
            const uint32_t offA = (((uint32_t)(2 * ks) + aCsel) ^ sw) << 4;   \
            const uint32_t offB = (((uint32_t)(2 * ks) + bCsel) ^ sw) << 4;   \
            uint32_t ah[2][4], bv[2][2];                                      \
            LDSM_X4(ah[0][0], ah[0][1], ah[0][2], ah[0][3], aB + aRow0 + offA); \
            LDSM_X4(ah[1][0], ah[1][1], ah[1][2], ah[1][3], aB + aRow1 + offA); \
            LDSM_X4(bv[0][0], bv[0][1], bv[1][0], bv[1][1], bB + bRow + offB);  \
            MMA_F16(G + 0,  ah[0], bv[0]);                                    \
            MMA_F16(G + 4,  ah[0], bv[1]);                                    \
            MMA_F16(G + 8,  ah[1], bv[0]);                                    \
            MMA_F16(G + 12, ah[1], bv[1]);                                    \
        }                                                                     \
    } while (0)

    if (t == 0) { ISSUE(0); ISSUE(1); ISSUE(2); ISSUE(3); }

    for (int s = 0; s < NSTG; s += 2) {
        COMPUTE_STAGE(s);
        COMPUTE_STAGE(s + 1);

        {   // fold G into O; A^T coeffs are 0/+-1 -> skip zeros
            int ij = s >> 1;
            int ii = ij >> 2, jj = ij & 3;
            float cy0 = c_a0[ii], cy1 = c_a1[ii];
            float cx0 = c_a0[jj], cx1 = c_a1[jj];
            float c00 = cy0 * cx0, c01 = cy0 * cx1;
            float c10 = cy1 * cx0, c11 = cy1 * cx1;
            if (c00 != 0.0f) {
                #pragma unroll
                for (int r = 0; r < 16; ++r) O0[r] = fmaf(c00, G[r], O0[r]);
            }
            if (c01 != 0.0f) {
                #pragma unroll
                for (int r = 0; r < 16; ++r) O1[r] = fmaf(c01, G[r], O1[r]);
            }
            if (c10 != 0.0f) {
                #pragma unroll
                for (int r = 0; r < 16; ++r) O2[r] = fmaf(c10, G[r], O2[r]);
            }
            if (c11 != 0.0f) {
                #pragma unroll
                for (int r = 0; r < 16; ++r) O3[r] = fmaf(c11, G[r], O3[r]);
            }
            #pragma unroll
            for (int r = 0; r < 16; ++r) G[r] = 0.0f;
        }
        __syncthreads();
        if (t == 0 && s + 4 < NSTG) { ISSUE(s + 4); ISSUE(s + 5); }
    }

    // ---- fused epilogue: inverse transform -> 4 output pixels per tile ----
    uint32_t* s_list = (uint32_t*)dsm;   // stage buffers dead

    #pragma unroll
    for (int mi = 0; mi < 2; ++mi) {
        #pragma unroll
        for (int e2 = 0; e2 < 2; ++e2) {
            int tl = mi * 16 + gid + 8 * e2;
            int trow = t0 + tl;
            if (trow >= TT) continue;
            int n  = trow / THW;
            int rr = trow % THW;
            int ty = rr / 55;
            int tx = rr % 55;
            int mbaseo = n * (Ho * Wo) + 2 * ty * Wo + 2 * tx;

            #pragma unroll
            for (int y = 0; y < 2; ++y) {
                #pragma unroll
                for (int xx = 0; xx < 2; ++xx) {
                    int m = mbaseo + y * Wo + xx;
                    float xn = g_xni[m];
                    const float* Oa = (y == 0) ? (xx == 0 ? O0 : O1)
                                               : (xx == 0 ? O2 : O3);
                    #pragma unroll
                    for (int ni = 0; ni < 2; ++ni) {
                        int cl = wno + ni * 8 + 2 * tig;   // local cout
                        int co = coB + cl;                 // global cout
                        int ri = mi * 8 + ni * 4 + 2 * e2;
                        float f0 = Oa[ri]     + s_bi[cl];
                        float f1 = Oa[ri + 1] + s_bi[cl + 1];
                        float y0 = f0 * xn * s_ws[cl];
                        float y1 = f1 * xn * s_ws[cl + 1];
                        if (fabsf(y0) < TAU) {
                            uint32_t i = atomicAdd(&s_cnt, 1u);
                            if (i < LISTCAP) s_list[i] = ((uint32_t)m << 8) | (uint32_t)co;
                        }
                        if (fabsf(y1) < TAU) {
                            uint32_t i = atomicAdd(&s_cnt, 1u);
                            if (i < LISTCAP) s_list[i] = ((uint32_t)m << 8) | (uint32_t)(co + 1);
                        }
                        float a0 = fabsf(y0) + 1e-12f;
                        float a1 = fabsf(y1) + 1e-12f;
                        float o0 = copysignf(__expf(s_ae[cl]     * __logf(a0)), f0);
                        float o1 = copysignf(__expf(s_ae[cl + 1] * __logf(a1)), f1);
                        *reinterpret_cast<float2*>(out + (size_t)m * Co + co) =
                            make_float2(o0, o1);
                    }
                }
            }
        }
    }

    __syncthreads();
    if (t == 0) {
        uint32_t cc = s_cnt < LISTCAP ? s_cnt : LISTCAP;
        s_cnt = cc;
        s_base = atomicAdd(&g_fix_cnt, cc);
    }
    __syncthreads();
    for (uint32_t i = t; i < s_cnt; i += 128) {
        uint32_t gidx = s_base + i;
        if (gidx < FIXCAP) g_fix_list[gidx] = s_list[i];
    }
    #undef ISSUE
    #undef COMPUTE_STAGE
}

// ---------------------------------------------------------------------------
// Kernel 5: exact fp32 recompute of flagged elements (warp per candidate)
// ---------------------------------------------------------------------------
__global__ void fixup_kernel(const float* __restrict__ x,
                             const float* __restrict__ bias,
                             float* __restrict__ out) {
    uint32_t total = g_fix_cnt;
    if (total > FIXCAP) total = FIXCAP;
    uint32_t wid   = (blockIdx.x * blockDim.x + threadIdx.x) >> 5;
    uint32_t nwarp = (gridDim.x * blockDim.x) >> 5;
    int lane = threadIdx.x & 31;

    for (uint32_t e = wid; e < total; e += nwarp) {
        uint32_t enc = g_fix_list[e];
        int m  = enc >> 8;
        int co = enc & 255;
        int n = m / (Ho * Wo);
        int r = m % (Ho * Wo);
        int h = r / Wo;
        int ww = r % Wo;
        int base = ((n * Hh + h) * Wd + ww) * Cc;

        float sum = 0.0f;
        #pragma unroll
        for (int g = 0; g < 9; ++g) {
            int ky = g / 3, kx = g - ky * 3;
            const float* xp = x + base + (ky * Wd + kx) * Cc;
            const float* wp = g_WT + (size_t)co * KK + g * Cc;
            #pragma unroll
            for (int ci = 0; ci < 4; ++ci) {
                int cch = ci * 32 + lane;
                sum = fmaf(xp[cch], wp[cch], sum);
            }
        }
        #pragma unroll
        for (int o = 16; o > 0; o >>= 1)
            sum += __shfl_xor_sync(0xffffffffu, sum, o);

        if (lane == 0) {
            float f  = sum + bias[co];
            float y  = f * g_xni[m] * g_ws[co];
            float ay = fabsf(y) + 1e-12f;
            float rr = __expf(g_ae[co] * __logf(ay));
            out[(size_t)m * Co + co] = copysignf(rr, f);
        }
    }
}

// ---------------------------------------------------------------------------
extern "C" void kernel_launch(void* const* d_in, const int* in_sizes, int n_in,
                              void* d_out, int out_size) {
    const float* x = (const float*)d_in[0];
    const float* W = (const float*)d_in[1];
    const float* b = (const float*)d_in[2];
    const float* p = (const float*)d_in[3];
    const float* q = (const float*)d_in[4];
    float* out = (float*)d_out;

    prep_kernel<<<385, 256>>>(W, p, q);                         // 1 (norms+wt)
    in_transform_kernel<<<(TT * 64) / 256, 256>>>(x);           // 2 (+sumsq)
    xnorm_kernel<<<(MM + 255) / 256, 256>>>(q);                 // 3

    static bool attr_set = false;
    if (!attr_set) {
        cudaFuncSetAttribute(conv_wino_kernel,
                             cudaFuncAttributeMaxDynamicSharedMemorySize, SMEM_DYN);
        attr_set = true;
    }
    conv_wino_kernel<<<dim3(NMB, 4), 128, SMEM_DYN>>>(b, out);  // 4 (profiled)

    fixup_kernel<<<512, 256>>>(x, b, out);                      // 5
}

// round 16
// speedup vs baseline: 1.1094x; 1.1094x over previous
#include <cuda_runtime.h>
#include <cuda_fp16.h>
#include <cstdint>
#include <math.h>

// ---------------------------------------------------------------------------
// Problem constants
// ---------------------------------------------------------------------------
#define Nn 16
#define Hh 112
#define Wd 112
#define Cc 128
#define Ho 110
#define Wo 110
#define Co 256
#define KK 1152                 // 3*3*128
#define MM (Nn*Ho*Wo)           // 193600
#define PIX (Nn*Hh*Wd)          // 200704
#define TT 48400                // winograd tiles: 16*55*55
#define THW 3025                // 55*55
#define NMB 1513                // M-blocks of 32 tiles (48416 padded)
#define FIXCAP (1u << 21)
#define TAU 5e-5f               // |y| threshold for exact fp32 recompute

// ---------------------------------------------------------------------------
// Scratch (device globals; no allocations allowed)
// ---------------------------------------------------------------------------
__device__ float g_s[PIX];
__device__ float g_xni[MM];
__device__ float g_ws[Co];
__device__ float g_ae[Co];
// A image: [stage s=ij*2+half][mblock b][4096B swizzled 32rows x 128B]
__device__ unsigned char g_AtI[32ull * NMB * 4096];
// B image: [stage s][32768B swizzled 256rows x 128B]
__device__ unsigned char g_BtI[32ull * 32768];
__device__ float  g_WT[Co * KK];             // W fp32 [co][k] (fixup)
__device__ uint32_t g_fix_list[FIXCAP];
__device__ uint32_t g_fix_cnt;

__constant__ float c_a0[4] = {1.f, 1.f,  1.f,  0.f};   // A^T row 0
__constant__ float c_a1[4] = {0.f, 1.f, -1.f, -1.f};   // A^T row 1

// ---------------------------------------------------------------------------
// Helpers
// ---------------------------------------------------------------------------
__device__ __forceinline__ uint32_t smem_u32(const void* p) {
    uint32_t a;
    asm("{ .reg .u64 t; cvta.to.shared.u64 t, %1; cvt.u32.u64 %0, t; }"
        : "=r"(a) : "l"(p));
    return a;
}

#define MMA_F16(cc, a, b)                                                     \
    asm volatile("mma.sync.aligned.m16n8k16.row.col.f32.f16.f16.f32 "        \
        "{%0,%1,%2,%3}, {%4,%5,%6,%7}, {%8,%9}, {%0,%1,%2,%3};"              \
        : "+f"((cc)[0]), "+f"((cc)[1]), "+f"((cc)[2]), "+f"((cc)[3])         \
        : "r"((a)[0]), "r"((a)[1]), "r"((a)[2]), "r"((a)[3]),                \
          "r"((b)[0]), "r"((b)[1]))

#define LDSM_X4(r0, r1, r2, r3, addr)                                        \
    asm volatile("ldmatrix.sync.aligned.m8n8.x4.shared.b16 {%0,%1,%2,%3}, [%4];" \
        : "=r"(r0), "=r"(r1), "=r"(r2), "=r"(r3) : "r"(addr))

#define BULK_CP(dst, src, bytes, mbar)                                        \
    asm volatile("cp.async.bulk.shared::cta.global.mbarrier::complete_tx::bytes " \
        "[%0], [%1], %2, [%3];"                                               \
        :: "r"(dst), "l"(src), "r"(bytes), "r"(mbar) : "memory")

#define MBARRIER_INIT(mbar, cnt) \
    asm volatile("mbarrier.init.shared.b64 [%0], %1;" \
                 :: "r"((uint32_t)(mbar)), "r"((uint32_t)(cnt)) : "memory")
#define MBARRIER_EXPECT_TX(mbar, bytes) \
    asm volatile("mbarrier.arrive.expect_tx.shared.b64 _, [%0], %1;" \
                 :: "r"((uint32_t)(mbar)), "r"((uint32_t)(bytes)) : "memory")
#define FENCE_ASYNC() asm volatile("fence.proxy.async.shared::cta;" ::: "memory")

#define MBARRIER_WAIT_PARITY(mbar_addr, phase_parity) do {                       \
    uint32_t _mbar = (uint32_t)(mbar_addr);                                      \
    uint32_t _parity = (uint32_t)(phase_parity);                                 \
    uint32_t _done;                                                              \
    asm volatile("{\n\t.reg .pred p;\n\t"                                        \
        "mbarrier.try_wait.parity.acquire.cta.shared::cta.b64 p, [%1], %2;\n\t"  \
        "selp.b32 %0, 1, 0, p;\n\t}"                                             \
        : "=r"(_done) : "r"(_mbar), "r"(_parity) : "memory");                    \
    if (!_done) {                                                                \
        asm volatile("{\n\t.reg .pred P1;\n\t"                                   \
            "WAIT_LOOP_%=:\n\t"                                                  \
            "mbarrier.try_wait.parity.acquire.cta.shared::cta.b64 P1, [%0], %1, 0x989680;\n\t" \
            "@P1 bra.uni WAIT_DONE_%=;\n\t"                                      \
            "bra.uni WAIT_LOOP_%=;\n\t"                                          \
            "WAIT_DONE_%=:\n\t}"                                                 \
            :: "r"(_mbar), "r"(_parity) : "memory");                             \
    }                                                                            \
} while (0)

// ---------------------------------------------------------------------------
// Kernel 1 (merged): blocks 0..255 = weight norms/exponents (+fix_cnt reset);
// blocks 256..383 = weight transform per input channel; block 384 = A pad.
// ---------------------------------------------------------------------------
__global__ void prep_kernel(const float* __restrict__ W,
                            const float* __restrict__ p,
                            const float* __restrict__ q) {
    int t = threadIdx.x;
    if (blockIdx.x < 256) {
        __shared__ float red[256];
        int c = blockIdx.x;
        if (c == 0 && t == 0) g_fix_cnt = 0;
        float s = 0.0f;
        for (int k = t; k < KK; k += 256) {
            float w = W[k * Co + c];
            s = fmaf(w, w, s);
        }
        red[t] = s; __syncthreads();
        for (int o = 128; o > 0; o >>= 1) {
            if (t < o) red[t] += red[t + o];
            __syncthreads();
        }
        if (t == 0) {
            float qq = q[0] * q[0] * 0.1f;
            g_ws[c] = 1.0f / (sqrtf(red[0]) + qq);
            g_ae[c] = p[c] * p[c] * 0.01f;
        }
        return;
    }
    if (blockIdx.x == 384) {
        for (int i = t; i < 32 * 2048 / 16; i += 256) {
            int s = i / 128;
            int j = (i % 128) * 16;
            *reinterpret_cast<uint4*>(
                g_AtI + ((size_t)s * NMB + (NMB - 1)) * 4096 + 2048 + j) =
                make_uint4(0, 0, 0, 0);
        }
        return;
    }
    int c  = blockIdx.x - 256;          // input channel 0..127
    int co = t;
    float g[3][3];
    #pragma unroll
    for (int r = 0; r < 3; ++r)
        #pragma unroll
        for (int s = 0; s < 3; ++s) {
            float w = W[((r * 3 + s) * Cc + c) * Co + co];
            g[r][s] = w;
            g_WT[(size_t)co * KK + (r * 3 + s) * Cc + c] = w;
        }
    float u[4][3];
    #pragma unroll
    for (int s = 0; s < 3; ++s) {
        u[0][s] = g[0][s];
        u[1][s] = 0.5f * (g[0][s] + g[1][s] + g[2][s]);
        u[2][s] = 0.5f * (g[0][s] - g[1][s] + g[2][s]);
        u[3][s] = g[2][s];
    }
    int half = c >> 6;
    int ch   = (c & 63) >> 3;
    int e    = c & 7;
    uint32_t off = (uint32_t)co * 128u + (uint32_t)((ch ^ (co & 7)) << 4) + e * 2;
    #pragma unroll
    for (int i = 0; i < 4; ++i) {
        float v[4];
        v[0] = u[i][0];
        v[1] = 0.5f * (u[i][0] + u[i][1] + u[i][2]);
        v[2] = 0.5f * (u[i][0] - u[i][1] + u[i][2]);
        v[3] = u[i][2];
        #pragma unroll
        for (int j = 0; j < 4; ++j) {
            int st = (i * 4 + j) * 2 + half;
            *reinterpret_cast<__half*>(g_BtI + (size_t)st * 32768 + off) =
                __float2half_rn(v[j]);
        }
    }
}

// ---------------------------------------------------------------------------
// Kernel 2: per-input-pixel sum of x^2 (one warp per pixel)
// ---------------------------------------------------------------------------
__global__ void sumsq_kernel(const float* __restrict__ x) {
    int pix  = blockIdx.x * 8 + (threadIdx.x >> 5);
    int lane = threadIdx.x & 31;
    const float4* xp = reinterpret_cast<const float4*>(x + (size_t)pix * Cc);
    float4 v = xp[lane];
    float s = v.x * v.x + v.y * v.y + v.z * v.z + v.w * v.w;
    #pragma unroll
    for (int o = 16; o > 0; o >>= 1) s += __shfl_xor_sync(0xffffffffu, s, o);
    if (lane == 0) g_s[pix] = s;
}

// ---------------------------------------------------------------------------
// Kernel 3 (merged): blocks < 12100 = input transform (2 ch/thread);
// blocks >= 12100 = 3x3 window sum -> inverse patch norm.
// ---------------------------------------------------------------------------
#define XF_BLKS 12100            // TT*64/256

__global__ void in_transform_kernel(const float* __restrict__ x,
                                    const float* __restrict__ q) {
    if (blockIdx.x >= XF_BLKS) {
        int idx = (blockIdx.x - XF_BLKS) * 256 + threadIdx.x;
        if (idx >= MM) return;
        int n = idx / (Ho * Wo);
        int r = idx % (Ho * Wo);
        int h = r / Wo;
        int w = r % Wo;
        const float* sp = g_s + ((size_t)n * Hh + h) * Wd + w;
        float sum = 0.0f;
        #pragma unroll
        for (int ky = 0; ky < 3; ++ky)
            sum += sp[ky * Wd] + sp[ky * Wd + 1] + sp[ky * Wd + 2];
        float qq = q[0] * q[0] * 0.1f;
        g_xni[idx] = 1.0f / (sqrtf(sum) + qq);
        return;
    }
    int idx = blockIdx.x * 256 + threadIdx.x;    // TT*64 exact
    int t  = idx >> 6;
    int cp = idx & 63;
    int c0 = cp * 2;
    int n  = t / THW;
    int rr = t % THW;
    int ty = rr / 55;
    int tx = rr % 55;
    const float* xp = x + (((size_t)n * Hh + 2 * ty) * Wd + 2 * tx) * Cc + c0;

    float da[4][4], db[4][4];
    #pragma unroll
    for (int r = 0; r < 4; ++r)
        #pragma unroll
        for (int s = 0; s < 4; ++s) {
            float2 v = *reinterpret_cast<const float2*>(xp + (r * Wd + s) * Cc);
            da[r][s] = v.x; db[r][s] = v.y;
        }

    float ua[4][4], ub[4][4];
    #pragma unroll
    for (int s = 0; s < 4; ++s) {
        ua[0][s] = da[0][s] - da[2][s];  ub[0][s] = db[0][s] - db[2][s];
        ua[1][s] = da[1][s] + da[2][s];  ub[1][s] = db[1][s] + db[2][s];
        ua[2][s] = da[2][s] - da[1][s];  ub[2][s] = db[2][s] - db[1][s];
        ua[3][s] = da[1][s] - da[3][s];  ub[3][s] = db[1][s] - db[3][s];
    }
    int blk  = t >> 5;
    int row  = t & 31;
    int half = c0 >> 6;
    int ch   = (c0 & 63) >> 3;
    int e    = c0 & 7;        // even
    uint32_t off = (uint32_t)row * 128u + (uint32_t)((ch ^ (row & 7)) << 4) + e * 2;
    #pragma unroll
    for (int i = 0; i < 4; ++i) {
        float va[4], vb[4];
        va[0] = ua[i][0] - ua[i][2];  vb[0] = ub[i][0] - ub[i][2];
        va[1] = ua[i][1] + ua[i][2];  vb[1] = ub[i][1] + ub[i][2];
        va[2] = ua[i][2] - ua[i][1];  vb[2] = ub[i][2] - ub[i][1];
        va[3] = ua[i][1] - ua[i][3];  vb[3] = ub[i][1] - ub[i][3];
        #pragma unroll
        for (int j = 0; j < 4; ++j) {
            int st = (i * 4 + j) * 2 + half;
            *reinterpret_cast<__half2*>(
                g_AtI + ((size_t)st * NMB + blk) * 4096 + off) =
                __halves2half2(__float2half_rn(va[j]), __float2half_rn(vb[j]));
        }
    }
}

// ---------------------------------------------------------------------------
// Kernel 4 (profiled slot): Winograd GEMM, N-quartered. CTA = 32 tiles x 64
// cout, 128 threads (4 warps x [32t x 16co]), grid (4, NMB) so the four
// N-quarters of one m-block are launch-adjacent -> A-image hits L2.
// Ring-4 bulk-copy pipeline, sync per ij phase.
// ---------------------------------------------------------------------------
#define NSTG 32
#define RG_B 4096
#define STG  12288              // A 4KB + B 8KB
#define RING 4
#define SMEM_DYN (RING * STG)   // 49152
#define LISTCAP 8192

extern __shared__ char dsm[];

__global__ void __launch_bounds__(128, 4)
conv_wino_kernel(const float* __restrict__ bias, float* __restrict__ out) {
    __shared__ float s_ws[64], s_ae[64], s_bi[64];
    __shared__ uint32_t s_cnt, s_base;
    __shared__ __align__(8) uint64_t s_mb[RING];

    const uint32_t sbase = smem_u32(dsm);
    const uint32_t mbase = smem_u32(s_mb);
    const int t    = threadIdx.x;
    const int w    = t >> 5;
    const int lane = t & 31;
    const int gid  = lane >> 2;
    const int tig  = lane & 3;
    const int b    = blockIdx.y;          // m-block (slow axis)
    const int nh   = blockIdx.x;          // N quarter 0..3 (fast axis)
    const int t0   = b * 32;
    const int wno  = w * 16;              // local cout base (0..48)
    const int coB  = nh * 64;             // global cout offset

    if (t < 64) {
        s_ws[t] = g_ws[coB + t];
        s_ae[t] = g_ae[coB + t];
        s_bi[t] = bias[coB + t];
    }
    if (t == 0) {
        s_cnt = 0;
        #pragma unroll
        for (int i = 0; i < RING; ++i) MBARRIER_INIT(mbase + i * 8, 1);
        FENCE_ASYNC();
    }
    __syncthreads();

    // ldmatrix invariants (verified R7-R15)
    const uint32_t sw    = lane & 7;
    const uint32_t aRow0 = (uint32_t)(lane & 15) * 128u;
    const uint32_t aRow1 = aRow0 + 16u * 128u;
    const uint32_t aCsel = (lane >> 4);
    const uint32_t bRow  = (uint32_t)(wno + ((lane >> 4) << 3) + (lane & 7)) * 128u;
    const uint32_t bCsel = (lane >> 3) & 1;

    float O0[16], O1[16], O2[16], O3[16], G[16];
    #pragma unroll
    for (int i = 0; i < 16; ++i) { O0[i]=0.f; O1[i]=0.f; O2[i]=0.f; O3[i]=0.f; G[i]=0.f; }

    #define ISSUE(s) do {                                                     \
        uint32_t buf = sbase + (uint32_t)((s) % RING) * STG;                  \
        uint32_t mb  = mbase + ((s) % RING) * 8;                              \
        MBARRIER_EXPECT_TX(mb, STG);                                          \
        BULK_CP(buf, g_AtI + ((size_t)(s) * NMB + b) * 4096, 4096u, mb);      \
        BULK_CP(buf + RG_B,                                                   \
                g_BtI + (size_t)(s) * 32768 + (size_t)nh * 8192, 8192u, mb);  \
    } while (0)

    #define COMPUTE_STAGE(s) do {                                             \
        MBARRIER_WAIT_PARITY(mbase + ((s) % RING) * 8, ((s) / RING) & 1);     \
        const uint32_t aB = sbase + (uint32_t)((s) % RING) * STG;             \
        const uint32_t bB = aB + RG_B;                                        \
        _Pragma("unroll")                                                     \
        for (int ks = 0; ks < 4; ++ks) {                                      \
            const uint32_t offA = (((uint32_t)(2 * ks) + aCsel) ^ sw) << 4;   \
            const uint32_t offB = (((uint32_t)(2 * ks) + bCsel) ^ sw) << 4;   \
            uint32_t ah[2][4], bv[2][2];                                      \
            LDSM_X4(ah[0][0], ah[0][1], ah[0][2], ah[0][3], aB + aRow0 + offA); \
            LDSM_X4(ah[1][0], ah[1][1], ah[1][2], ah[1][3], aB + aRow1 + offA); \
            LDSM_X4(bv[0][0], bv[0][1], bv[1][0], bv[1][1], bB + bRow + offB);  \
            MMA_F16(G + 0,  ah[0], bv[0]);                                    \
            MMA_F16(G + 4,  ah[0], bv[1]);                                    \
            MMA_F16(G + 8,  ah[1], bv[0]);                                    \
            MMA_F16(G + 12, ah[1], bv[1]);                                    \
        }                                                                     \
    } while (0)

    if (t == 0) { ISSUE(0); ISSUE(1); ISSUE(2); ISSUE(3); }

    for (int s = 0; s < NSTG; s += 2) {
        COMPUTE_STAGE(s);
        COMPUTE_STAGE(s + 1);

        {   // fold G into O; A^T coeffs are 0/+-1 -> skip zeros
            int ij = s >> 1;
            int ii = ij >> 2, jj = ij & 3;
            float cy0 = c_a0[ii], cy1 = c_a1[ii];
            float cx0 = c_a0[jj], cx1 = c_a1[jj];
            float c00 = cy0 * cx0, c01 = cy0 * cx1;
            float c10 = cy1 * cx0, c11 = cy1 * cx1;
            if (c00 != 0.0f) {
                #pragma unroll
                for (int r = 0; r < 16; ++r) O0[r] = fmaf(c00, G[r], O0[r]);
            }
            if (c01 != 0.0f) {
                #pragma unroll
                for (int r = 0; r < 16; ++r) O1[r] = fmaf(c01, G[r], O1[r]);
            }
            if (c10 != 0.0f) {
                #pragma unroll
                for (int r = 0; r < 16; ++r) O2[r] = fmaf(c10, G[r], O2[r]);
            }
            if (c11 != 0.0f) {
                #pragma unroll
                for (int r = 0; r < 16; ++r) O3[r] = fmaf(c11, G[r], O3[r]);
            }
            #pragma unroll
            for (int r = 0; r < 16; ++r) G[r] = 0.0f;
        }
        __syncthreads();
        if (t == 0 && s + 4 < NSTG) { ISSUE(s + 4); ISSUE(s + 5); }
    }

    // ---- fused epilogue: inverse transform -> 4 output pixels per tile ----
    uint32_t* s_list = (uint32_t*)dsm;   // stage buffers dead

    #pragma unroll
    for (int mi = 0; mi < 2; ++mi) {
        #pragma unroll
        for (int e2 = 0; e2 < 2; ++e2) {
            int tl = mi * 16 + gid + 8 * e2;
            int trow = t0 + tl;
            if (trow >= TT) continue;
            int n  = trow / THW;
            int rr = trow % THW;
            int ty = rr / 55;
            int tx = rr % 55;
            int mbaseo = n * (Ho * Wo) + 2 * ty * Wo + 2 * tx;

            #pragma unroll
            for (int y = 0; y < 2; ++y) {
                #pragma unroll
                for (int xx = 0; xx < 2; ++xx) {
                    int m = mbaseo + y * Wo + xx;
                    float xn = g_xni[m];
                    const float* Oa = (y == 0) ? (xx == 0 ? O0 : O1)
                                               : (xx == 0 ? O2 : O3);
                    #pragma unroll
                    for (int ni = 0; ni < 2; ++ni) {
                        int cl = wno + ni * 8 + 2 * tig;   // local cout
                        int co = coB + cl;                 // global cout
                        int ri = mi * 8 + ni * 4 + 2 * e2;
                        float f0 = Oa[ri]     + s_bi[cl];
                        float f1 = Oa[ri + 1] + s_bi[cl + 1];
                        float y0 = f0 * xn * s_ws[cl];
                        float y1 = f1 * xn * s_ws[cl + 1];
                        if (fabsf(y0) < TAU) {
                            uint32_t i = atomicAdd(&s_cnt, 1u);
                            if (i < LISTCAP) s_list[i] = ((uint32_t)m << 8) | (uint32_t)co;
                        }
                        if (fabsf(y1) < TAU) {
                            uint32_t i = atomicAdd(&s_cnt, 1u);
                            if (i < LISTCAP) s_list[i] = ((uint32_t)m << 8) | (uint32_t)(co + 1);
                        }
                        float a0 = fabsf(y0) + 1e-12f;
                        float a1 = fabsf(y1) + 1e-12f;
                        float o0 = copysignf(__expf(s_ae[cl]     * __logf(a0)), f0);
                        float o1 = copysignf(__expf(s_ae[cl + 1] * __logf(a1)), f1);
                        *reinterpret_cast<float2*>(out + (size_t)m * Co + co) =
                            make_float2(o0, o1);
                    }
                }
            }
        }
    }

    __syncthreads();
    if (t == 0) {
        uint32_t cc = s_cnt < LISTCAP ? s_cnt : LISTCAP;
        s_cnt = cc;
        s_base = atomicAdd(&g_fix_cnt, cc);
    }
    __syncthreads();
    for (uint32_t i = t; i < s_cnt; i += 128) {
        uint32_t gidx = s_base + i;
        if (gidx < FIXCAP) g_fix_list[gidx] = s_list[i];
    }
    #undef ISSUE
    #undef COMPUTE_STAGE
}

// ---------------------------------------------------------------------------
// Kernel 5: exact fp32 recompute of flagged elements (warp per candidate)
// ---------------------------------------------------------------------------
__global__ void fixup_kernel(const float* __restrict__ x,
                             const float* __restrict__ bias,
                             float* __restrict__ out) {
    uint32_t total = g_fix_cnt;
    if (total > FIXCAP) total = FIXCAP;
    uint32_t wid   = (blockIdx.x * blockDim.x + threadIdx.x) >> 5;
    uint32_t nwarp = (gridDim.x * blockDim.x) >> 5;
    int lane = threadIdx.x & 31;

    for (uint32_t e = wid; e < total; e += nwarp) {
        uint32_t enc = g_fix_list[e];
        int m  = enc >> 8;
        int co = enc & 255;
        int n = m / (Ho * Wo);
        int r = m % (Ho * Wo);
        int h = r / Wo;
        int ww = r % Wo;
        int base = ((n * Hh + h) * Wd + ww) * Cc;

        float sum = 0.0f;
        #pragma unroll
        for (int g = 0; g < 9; ++g) {
            int ky = g / 3, kx = g - ky * 3;
            const float* xp = x + base + (ky * Wd + kx) * Cc;
            const float* wp = g_WT + (size_t)co * KK + g * Cc;
            #pragma unroll
            for (int ci = 0; ci < 4; ++ci) {
                int cch = ci * 32 + lane;
                sum = fmaf(xp[cch], wp[cch], sum);
            }
        }
        #pragma unroll
        for (int o = 16; o > 0; o >>= 1)
            sum += __shfl_xor_sync(0xffffffffu, sum, o);

        if (lane == 0) {
            float f  = sum + bias[co];
            float y  = f * g_xni[m] * g_ws[co];
            float ay = fabsf(y) + 1e-12f;
            float rr = __expf(g_ae[co] * __logf(ay));
            out[(size_t)m * Co + co] = copysignf(rr, f);
        }
    }
}

// ---------------------------------------------------------------------------
extern "C" void kernel_launch(void* const* d_in, const int* in_sizes, int n_in,
                              void* d_out, int out_size) {
    const float* x = (const float*)d_in[0];
    const float* W = (const float*)d_in[1];
    const float* b = (const float*)d_in[2];
    const float* p = (const float*)d_in[3];
    const float* q = (const float*)d_in[4];
    float* out = (float*)d_out;

    prep_kernel<<<385, 256>>>(W, p, q);                         // 1 (norms+wt)
    sumsq_kernel<<<PIX / 8, 256>>>(x);                          // 2
    in_transform_kernel<<<XF_BLKS + (MM + 255) / 256, 256>>>(x, q); // 3 (+xnorm)

    static bool attr_set = false;
    if (!attr_set) {
        cudaFuncSetAttribute(conv_wino_kernel,
                             cudaFuncAttributeMaxDynamicSharedMemorySize, SMEM_DYN);
        attr_set = true;
    }
    conv_wino_kernel<<<dim3(4, NMB), 128, SMEM_DYN>>>(b, out);  // 4 (profiled)

    fixup_kernel<<<512, 256>>>(x, b, out);                      // 5
}

// round 17
// speedup vs baseline: 1.1133x; 1.0035x over previous
#include <cuda_runtime.h>
#include <cuda_fp16.h>
#include <cstdint>
#include <math.h>

// ---------------------------------------------------------------------------
// Problem constants
// ---------------------------------------------------------------------------
#define Nn 16
#define Hh 112
#define Wd 112
#define Cc 128
#define Ho 110
#define Wo 110
#define Co 256
#define KK 1152                 // 3*3*128
#define MM (Nn*Ho*Wo)           // 193600
#define PIX (Nn*Hh*Wd)          // 200704
#define TT 48400                // winograd tiles: 16*55*55
#define THW 3025                // 55*55
#define NMB 1513                // M-blocks of 32 tiles (48416 padded)
#define FIXCAP (1u << 21)
#define TAU 5e-5f               // |y| threshold for exact fp32 recompute

// ---------------------------------------------------------------------------
// Scratch (device globals; no allocations allowed)
// ---------------------------------------------------------------------------
__device__ float g_s[PIX];
__device__ float g_xni[MM];
__device__ float g_ws[Co];
__device__ float g_ae[Co];
// A image: [stage s=ij*2+half][mblock b][4096B swizzled 32rows x 128B]
__device__ unsigned char g_AtI[32ull * NMB * 4096];
// B image: [stage s][32768B swizzled 256rows x 128B]
__device__ unsigned char g_BtI[32ull * 32768];
__device__ float  g_WT[Co * KK];             // W fp32 [co][k] (fixup)
__device__ uint32_t g_fix_list[FIXCAP];
__device__ uint32_t g_fix_cnt;

__constant__ float c_a0[4] = {1.f, 1.f,  1.f,  0.f};   // A^T row 0
__constant__ float c_a1[4] = {0.f, 1.f, -1.f, -1.f};   // A^T row 1

// ---------------------------------------------------------------------------
// Helpers
// ---------------------------------------------------------------------------
__device__ __forceinline__ uint32_t smem_u32(const void* p) {
    uint32_t a;
    asm("{ .reg .u64 t; cvta.to.shared.u64 t, %1; cvt.u32.u64 %0, t; }"
        : "=r"(a) : "l"(p));
    return a;
}
__device__ __forceinline__ float4 f4add(float4 a, float4 b) {
    return make_float4(a.x + b.x, a.y + b.y, a.z + b.z, a.w + b.w);
}
__device__ __forceinline__ float4 f4sub(float4 a, float4 b) {
    return make_float4(a.x - b.x, a.y - b.y, a.z - b.z, a.w - b.w);
}

#define MMA_F16(cc, a, b)                                                     \
    asm volatile("mma.sync.aligned.m16n8k16.row.col.f32.f16.f16.f32 "        \
        "{%0,%1,%2,%3}, {%4,%5,%6,%7}, {%8,%9}, {%0,%1,%2,%3};"              \
        : "+f"((cc)[0]), "+f"((cc)[1]), "+f"((cc)[2]), "+f"((cc)[3])         \
        : "r"((a)[0]), "r"((a)[1]), "r"((a)[2]), "r"((a)[3]),                \
          "r"((b)[0]), "r"((b)[1]))

#define LDSM_X4(r0, r1, r2, r3, addr)                                        \
    asm volatile("ldmatrix.sync.aligned.m8n8.x4.shared.b16 {%0,%1,%2,%3}, [%4];" \
        : "=r"(r0), "=r"(r1), "=r"(r2), "=r"(r3) : "r"(addr))

#define BULK_CP(dst, src, bytes, mbar)                                        \
    asm volatile("cp.async.bulk.shared::cta.global.mbarrier::complete_tx::bytes " \
        "[%0], [%1], %2, [%3];"                                               \
        :: "r"(dst), "l"(src), "r"(bytes), "r"(mbar) : "memory")

#define MBARRIER_INIT(mbar, cnt) \
    asm volatile("mbarrier.init.shared.b64 [%0], %1;" \
                 :: "r"((uint32_t)(mbar)), "r"((uint32_t)(cnt)) : "memory")
#define MBARRIER_EXPECT_TX(mbar, bytes) \
    asm volatile("mbarrier.arrive.expect_tx.shared.b64 _, [%0], %1;" \
                 :: "r"((uint32_t)(mbar)), "r"((uint32_t)(bytes)) : "memory")
#define FENCE_ASYNC() asm volatile("fence.proxy.async.shared::cta;" ::: "memory")

#define MBARRIER_WAIT_PARITY(mbar_addr, phase_parity) do {                       \
    uint32_t _mbar = (uint32_t)(mbar_addr);                                      \
    uint32_t _parity = (uint32_t)(phase_parity);                                 \
    uint32_t _done;                                                              \
    asm volatile("{\n\t.reg .pred p;\n\t"                                        \
        "mbarrier.try_wait.parity.acquire.cta.shared::cta.b64 p, [%1], %2;\n\t"  \
        "selp.b32 %0, 1, 0, p;\n\t}"                                             \
        : "=r"(_done) : "r"(_mbar), "r"(_parity) : "memory");                    \
    if (!_done) {                                                                \
        asm volatile("{\n\t.reg .pred P1;\n\t"                                   \
            "WAIT_LOOP_%=:\n\t"                                                  \
            "mbarrier.try_wait.parity.acquire.cta.shared::cta.b64 P1, [%0], %1, 0x989680;\n\t" \
            "@P1 bra.uni WAIT_DONE_%=;\n\t"                                      \
            "bra.uni WAIT_LOOP_%=;\n\t"                                          \
            "WAIT_DONE_%=:\n\t}"                                                 \
            :: "r"(_mbar), "r"(_parity) : "memory");                             \
    }                                                                            \
} while (0)

// ---------------------------------------------------------------------------
// Kernel 1 (merged): blocks 0..255 = weight norms/exponents (+fix_cnt reset);
// blocks 256..383 = weight transform per input channel; block 384 = A pad.
// ---------------------------------------------------------------------------
__global__ void prep_kernel(const float* __restrict__ W,
                            const float* __restrict__ p,
                            const float* __restrict__ q) {
    int t = threadIdx.x;
    if (blockIdx.x < 256) {
        __shared__ float red[256];
        int c = blockIdx.x;
        if (c == 0 && t == 0) g_fix_cnt = 0;
        float s = 0.0f;
        for (int k = t; k < KK; k += 256) {
            float w = W[k * Co + c];
            s = fmaf(w, w, s);
        }
        red[t] = s; __syncthreads();
        for (int o = 128; o > 0; o >>= 1) {
            if (t < o) red[t] += red[t + o];
            __syncthreads();
        }
        if (t == 0) {
            float qq = q[0] * q[0] * 0.1f;
            g_ws[c] = 1.0f / (sqrtf(red[0]) + qq);
            g_ae[c] = p[c] * p[c] * 0.01f;
        }
        return;
    }
    if (blockIdx.x == 384) {
        for (int i = t; i < 32 * 2048 / 16; i += 256) {
            int s = i / 128;
            int j = (i % 128) * 16;
            *reinterpret_cast<uint4*>(
                g_AtI + ((size_t)s * NMB + (NMB - 1)) * 4096 + 2048 + j) =
                make_uint4(0, 0, 0, 0);
        }
        return;
    }
    int c  = blockIdx.x - 256;          // input channel 0..127
    int co = t;
    float g[3][3];
    #pragma unroll
    for (int r = 0; r < 3; ++r)
        #pragma unroll
        for (int s = 0; s < 3; ++s) {
            float w = W[((r * 3 + s) * Cc + c) * Co + co];
            g[r][s] = w;
            g_WT[(size_t)co * KK + (r * 3 + s) * Cc + c] = w;
        }
    float u[4][3];
    #pragma unroll
    for (int s = 0; s < 3; ++s) {
        u[0][s] = g[0][s];
        u[1][s] = 0.5f * (g[0][s] + g[1][s] + g[2][s]);
        u[2][s] = 0.5f * (g[0][s] - g[1][s] + g[2][s]);
        u[3][s] = g[2][s];
    }
    int half = c >> 6;
    int ch   = (c & 63) >> 3;
    int e    = c & 7;
    uint32_t off = (uint32_t)co * 128u + (uint32_t)((ch ^ (co & 7)) << 4) + e * 2;
    #pragma unroll
    for (int i = 0; i < 4; ++i) {
        float v[4];
        v[0] = u[i][0];
        v[1] = 0.5f * (u[i][0] + u[i][1] + u[i][2]);
        v[2] = 0.5f * (u[i][0] - u[i][1] + u[i][2]);
        v[3] = u[i][2];
        #pragma unroll
        for (int j = 0; j < 4; ++j) {
            int st = (i * 4 + j) * 2 + half;
            *reinterpret_cast<__half*>(g_BtI + (size_t)st * 32768 + off) =
                __float2half_rn(v[j]);
        }
    }
}

// ---------------------------------------------------------------------------
// Kernel 2: per-input-pixel sum of x^2 (one warp per pixel)
// ---------------------------------------------------------------------------
__global__ void sumsq_kernel(const float* __restrict__ x) {
    int pix  = blockIdx.x * 8 + (threadIdx.x >> 5);
    int lane = threadIdx.x & 31;
    const float4* xp = reinterpret_cast<const float4*>(x + (size_t)pix * Cc);
    float4 v = xp[lane];
    float s = v.x * v.x + v.y * v.y + v.z * v.z + v.w * v.w;
    #pragma unroll
    for (int o = 16; o > 0; o >>= 1) s += __shfl_xor_sync(0xffffffffu, s, o);
    if (lane == 0) g_s[pix] = s;
}

// ---------------------------------------------------------------------------
// Kernel 3 (merged): blocks < 6050 = input transform (4 ch/thread, float4);
// blocks >= 6050 = 3x3 window sum -> inverse patch norm.
// ---------------------------------------------------------------------------
#define XF_BLKS 6050             // TT*32/256

__global__ void in_transform_kernel(const float* __restrict__ x,
                                    const float* __restrict__ q) {
    if (blockIdx.x >= XF_BLKS) {
        int idx = (blockIdx.x - XF_BLKS) * 256 + threadIdx.x;
        if (idx >= MM) return;
        int n = idx / (Ho * Wo);
        int r = idx % (Ho * Wo);
        int h = r / Wo;
        int w = r % Wo;
        const float* sp = g_s + ((size_t)n * Hh + h) * Wd + w;
        float sum = 0.0f;
        #pragma unroll
        for (int ky = 0; ky < 3; ++ky)
            sum += sp[ky * Wd] + sp[ky * Wd + 1] + sp[ky * Wd + 2];
        float qq = q[0] * q[0] * 0.1f;
        g_xni[idx] = 1.0f / (sqrtf(sum) + qq);
        return;
    }
    int idx = blockIdx.x * 256 + threadIdx.x;    // TT*32 exact
    int t  = idx >> 5;
    int cp = idx & 31;
    int c0 = cp * 4;
    int n  = t / THW;
    int rr = t % THW;
    int ty = rr / 55;
    int tx = rr % 55;
    const float* xp = x + (((size_t)n * Hh + 2 * ty) * Wd + 2 * tx) * Cc + c0;

    float4 d[4][4];
    #pragma unroll
    for (int r = 0; r < 4; ++r)
        #pragma unroll
        for (int s = 0; s < 4; ++s)
            d[r][s] = *reinterpret_cast<const float4*>(xp + (r * Wd + s) * Cc);

    // row transform B^T d, in place (per column)
    #pragma unroll
    for (int s = 0; s < 4; ++s) {
        float4 t2 = f4sub(d[2][s], d[1][s]);   // u2 (from original d1,d2)
        d[0][s] = f4sub(d[0][s], d[2][s]);     // u0
        d[3][s] = f4sub(d[1][s], d[3][s]);     // u3
        d[1][s] = f4add(d[1][s], d[2][s]);     // u1
        d[2][s] = t2;
    }

    int blk  = t >> 5;
    int row  = t & 31;
    int half = c0 >> 6;
    int ch   = (c0 & 63) >> 3;
    int e    = c0 & 7;        // 0 or 4
    uint32_t off = (uint32_t)row * 128u + (uint32_t)((ch ^ (row & 7)) << 4) + e * 2;

    // column transform u B and store 4 fp16 channels (8B) per (i,j)
    #pragma unroll
    for (int i = 0; i < 4; ++i) {
        float4 v[4];
        v[0] = f4sub(d[i][0], d[i][2]);
        v[1] = f4add(d[i][1], d[i][2]);
        v[2] = f4sub(d[i][2], d[i][1]);
        v[3] = f4sub(d[i][1], d[i][3]);
        #pragma unroll
        for (int j = 0; j < 4; ++j) {
            int st = (i * 4 + j) * 2 + half;
            __half2 lo = __halves2half2(__float2half_rn(v[j].x),
                                        __float2half_rn(v[j].y));
            __half2 hi = __halves2half2(__float2half_rn(v[j].z),
                                        __float2half_rn(v[j].w));
            uint2 pk;
            pk.x = *reinterpret_cast<uint32_t*>(&lo);
            pk.y = *reinterpret_cast<uint32_t*>(&hi);
            *reinterpret_cast<uint2*>(
                g_AtI + ((size_t)st * NMB + blk) * 4096 + off) = pk;
        }
    }
}

// ---------------------------------------------------------------------------
// Kernel 4 (profiled slot): Winograd GEMM, N-quartered. CTA = 32 tiles x 64
// cout, 128 threads (4 warps x [32t x 16co]), grid (4, NMB) so the four
// N-quarters of one m-block are launch-adjacent -> A-image hits L2.
// Ring-4 bulk-copy pipeline, sync per ij phase. (Unchanged from R16.)
// ---------------------------------------------------------------------------
#define NSTG 32
#define RG_B 4096
#define STG  12288              // A 4KB + B 8KB
#define RING 4
#define SMEM_DYN (RING * STG)   // 49152
#define LISTCAP 8192

extern __shared__ char dsm[];

__global__ void __launch_bounds__(128, 4)
conv_wino_kernel(const float* __restrict__ bias, float* __restrict__ out) {
    __shared__ float s_ws[64], s_ae[64], s_bi[64];
    __shared__ uint32_t s_cnt, s_base;
    __shared__ __align__(8) uint64_t s_mb[RING];

    const uint32_t sbase = smem_u32(dsm);
    const uint32_t mbase = smem_u32(s_mb);
    const int t    = threadIdx.x;
    const int w    = t >> 5;
    const int lane = t & 31;
    const int gid  = lane >> 2;
    const int tig  = lane & 3;
    const int b    = blockIdx.y;          // m-block (slow axis)
    const int nh   = blockIdx.x;          // N quarter 0..3 (fast axis)
    const int t0   = b * 32;
    const int wno  = w * 16;              // local cout base (0..48)
    const int coB  = nh * 64;             // global cout offset

    if (t < 64) {
        s_ws[t] = g_ws[coB + t];
        s_ae[t] = g_ae[coB + t];
        s_bi[t] = bias[coB + t];
    }
    if (t == 0) {
        s_cnt = 0;
        #pragma unroll
        for (int i = 0; i < RING; ++i) MBARRIER_INIT(mbase + i * 8, 1);
        FENCE_ASYNC();
    }
    __syncthreads();

    // ldmatrix invariants (verified R7-R16)
    const uint32_t sw    = lane & 7;
    const uint32_t aRow0 = (uint32_t)(lane & 15) * 128u;
    const uint32_t aRow1 = aRow0 + 16u * 128u;
    const uint32_t aCsel = (lane >> 4);
    const uint32_t bRow  = (uint32_t)(wno + ((lane >> 4) << 3) + (lane & 7)) * 128u;
    const uint32_t bCsel = (lane >> 3) & 1;

    float O0[16], O1[16], O2[16], O3[16], G[16];
    #pragma unroll
    for (int i = 0; i < 16; ++i) { O0[i]=0.f; O1[i]=0.f; O2[i]=0.f; O3[i]=0.f; G[i]=0.f; }

    #define ISSUE(s) do {                                                     \
        uint32_t buf = sbase + (uint32_t)((s) % RING) * STG;                  \
        uint32_t mb  = mbase + ((s) % RING) * 8;                              \
        MBARRIER_EXPECT_TX(mb, STG);                                          \
        BULK_CP(buf, g_AtI + ((size_t)(s) * NMB + b) * 4096, 4096u, mb);      \
        BULK_CP(buf + RG_B,                                                   \
                g_BtI + (size_t)(s) * 32768 + (size_t)nh * 8192, 8192u, mb);  \
    } while (0)

    #define COMPUTE_STAGE(s) do {                                             \
        MBARRIER_WAIT_PARITY(mbase + ((s) % RING) * 8, ((s) / RING) & 1);     \
        const uint32_t aB = sbase + (uint32_t)((s) % RING) * STG;             \
        const uint32_t bB = aB + RG_B;                                        \
        _Pragma("unroll")                                                     \
        for (int ks = 0; ks < 4; ++ks) {                                      \
            const uint32_t offA = (((uint32_t)(2 * ks) + aCsel) ^ sw) << 4;   \
            const uint32_t offB = (((uint32_t)(2 * ks) + bCsel) ^ sw) << 4;   \
            uint32_t ah[2][4], bv[2][2];                                      \
            LDSM_X4(ah[0][0], ah[0][1], ah[0][2], ah[0][3], aB + aRow0 + offA); \
            LDSM_X4(ah[1][0], ah[1][1], ah[1][2], ah[1][3], aB + aRow1 + offA); \
            LDSM_X4(bv[0][0], bv[0][1], bv[1][0], bv[1][1], bB + bRow + offB);  \
            MMA_F16(G + 0,  ah[0], bv[0]);                                    \
            MMA_F16(G + 4,  ah[0], bv[1]);                                    \
            MMA_F16(G + 8,  ah[1], bv[0]);                                    \
            MMA_F16(G + 12, ah[1], bv[1]);                                    \
        }                                                                     \
    } while (0)

    if (t == 0) { ISSUE(0); ISSUE(1); ISSUE(2); ISSUE(3); }

    for (int s = 0; s < NSTG; s += 2) {
        COMPUTE_STAGE(s);
        COMPUTE_STAGE(s + 1);

        {   // fold G into O; A^T coeffs are 0/+-1 -> skip zeros
            int ij = s >> 1;
            int ii = ij >> 2, jj = ij & 3;
            float cy0 = c_a0[ii], cy1 = c_a1[ii];
            float cx0 = c_a0[jj], cx1 = c_a1[jj];
            float c00 = cy0 * cx0, c01 = cy0 * cx1;
            float c10 = cy1 * cx0, c11 = cy1 * cx1;
            if (c00 != 0.0f) {
                #pragma unroll
                for (int r = 0; r < 16; ++r) O0[r] = fmaf(c00, G[r], O0[r]);
            }
            if (c01 != 0.0f) {
                #pragma unroll
                for (int r = 0; r < 16; ++r) O1[r] = fmaf(c01, G[r], O1[r]);
            }
            if (c10 != 0.0f) {
                #pragma unroll
                for (int r = 0; r < 16; ++r) O2[r] = fmaf(c10, G[r], O2[r]);
            }
            if (c11 != 0.0f) {
                #pragma unroll
                for (int r = 0; r < 16; ++r) O3[r] = fmaf(c11, G[r], O3[r]);
            }
            #pragma unroll
            for (int r = 0; r < 16; ++r) G[r] = 0.0f;
        }
        __syncthreads();
        if (t == 0 && s + 4 < NSTG) { ISSUE(s + 4); ISSUE(s + 5); }
    }

    // ---- fused epilogue: inverse transform -> 4 output pixels per tile ----
    uint32_t* s_list = (uint32_t*)dsm;   // stage buffers dead

    #pragma unroll
    for (int mi = 0; mi < 2; ++mi) {
        #pragma unroll
        for (int e2 = 0; e2 < 2; ++e2) {
            int tl = mi * 16 + gid + 8 * e2;
            int trow = t0 + tl;
            if (trow >= TT) continue;
            int n  = trow / THW;
            int rr = trow % THW;
            int ty = rr / 55;
            int tx = rr % 55;
            int mbaseo = n * (Ho * Wo) + 2 * ty * Wo + 2 * tx;

            #pragma unroll
            for (int y = 0; y < 2; ++y) {
                #pragma unroll
                for (int xx = 0; xx < 2; ++xx) {
                    int m = mbaseo + y * Wo + xx;
                    float xn = g_xni[m];
                    const float* Oa = (y == 0) ? (xx == 0 ? O0 : O1)
                                               : (xx == 0 ? O2 : O3);
                    #pragma unroll
                    for (int ni = 0; ni < 2; ++ni) {
                        int cl = wno + ni * 8 + 2 * tig;   // local cout
                        int co = coB + cl;                 // global cout
                        int ri = mi * 8 + ni * 4 + 2 * e2;
                        float f0 = Oa[ri]     + s_bi[cl];
                        float f1 = Oa[ri + 1] + s_bi[cl + 1];
                        float y0 = f0 * xn * s_ws[cl];
                        float y1 = f1 * xn * s_ws[cl + 1];
                        if (fabsf(y0) < TAU) {
                            uint32_t i = atomicAdd(&s_cnt, 1u);
                            if (i < LISTCAP) s_list[i] = ((uint32_t)m << 8) | (uint32_t)co;
                        }
                        if (fabsf(y1) < TAU) {
                            uint32_t i = atomicAdd(&s_cnt, 1u);
                            if (i < LISTCAP) s_list[i] = ((uint32_t)m << 8) | (uint32_t)(co + 1);
                        }
                        float a0 = fabsf(y0) + 1e-12f;
                        float a1 = fabsf(y1) + 1e-12f;
                        float o0 = copysignf(__expf(s_ae[cl]     * __logf(a0)), f0);
                        float o1 = copysignf(__expf(s_ae[cl + 1] * __logf(a1)), f1);
                        *reinterpret_cast<float2*>(out + (size_t)m * Co + co) =
                            make_float2(o0, o1);
                    }
                }
            }
        }
    }

    __syncthreads();
    if (t == 0) {
        uint32_t cc = s_cnt < LISTCAP ? s_cnt : LISTCAP;
        s_cnt = cc;
        s_base = atomicAdd(&g_fix_cnt, cc);
    }
    __syncthreads();
    for (uint32_t i = t; i < s_cnt; i += 128) {
        uint32_t gidx = s_base + i;
        if (gidx < FIXCAP) g_fix_list[gidx] = s_list[i];
    }
    #undef ISSUE
    #undef COMPUTE_STAGE
}

// ---------------------------------------------------------------------------
// Kernel 5: exact fp32 recompute of flagged elements (warp per candidate)
// ---------------------------------------------------------------------------
__global__ void fixup_kernel(const float* __restrict__ x,
                             const float* __restrict__ bias,
                             float* __restrict__ out) {
    uint32_t total = g_fix_cnt;
    if (total > FIXCAP) total = FIXCAP;
    uint32_t wid   = (blockIdx.x * blockDim.x + threadIdx.x) >> 5;
    uint32_t nwarp = (gridDim.x * blockDim.x) >> 5;
    int lane = threadIdx.x & 31;

    for (uint32_t e = wid; e < total; e += nwarp) {
        uint32_t enc = g_fix_list[e];
        int m  = enc >> 8;
        int co = enc & 255;
        int n = m / (Ho * Wo);
        int r = m % (Ho * Wo);
        int h = r / Wo;
        int ww = r % Wo;
        int base = ((n * Hh + h) * Wd + ww) * Cc;

        float sum = 0.0f;
        #pragma unroll
        for (int g = 0; g < 9; ++g) {
            int ky = g / 3, kx = g - ky * 3;
            const float* xp = x + base + (ky * Wd + kx) * Cc;
            const float* wp = g_WT + (size_t)co * KK + g * Cc;
            #pragma unroll
            for (int ci = 0; ci < 4; ++ci) {
                int cch = ci * 32 + lane;
                sum = fmaf(xp[cch], wp[cch], sum);
            }
        }
        #pragma unroll
        for (int o = 16; o > 0; o >>= 1)
            sum += __shfl_xor_sync(0xffffffffu, sum, o);

        if (lane == 0) {
            float f  = sum + bias[co];
            float y  = f * g_xni[m] * g_ws[co];
            float ay = fabsf(y) + 1e-12f;
            float rr = __expf(g_ae[co] * __logf(ay));
            out[(size_t)m * Co + co] = copysignf(rr, f);
        }
    }
}

// ---------------------------------------------------------------------------
extern "C" void kernel_launch(void* const* d_in, const int* in_sizes, int n_in,
                              void* d_out, int out_size) {
    const float* x = (const float*)d_in[0];
    const float* W = (const float*)d_in[1];
    const float* b = (const float*)d_in[2];
    const float* p = (const float*)d_in[3];
    const float* q = (const float*)d_in[4];
    float* out = (float*)d_out;

    prep_kernel<<<385, 256>>>(W, p, q);                         // 1 (norms+wt)
    sumsq_kernel<<<PIX / 8, 256>>>(x);                          // 2
    in_transform_kernel<<<XF_BLKS + (MM + 255) / 256, 256>>>(x, q); // 3 (+xnorm)

    static bool attr_set = false;
    if (!attr_set) {
        cudaFuncSetAttribute(conv_wino_kernel,
                             cudaFuncAttributeMaxDynamicSharedMemorySize, SMEM_DYN);
        attr_set = true;
    }
    conv_wino_kernel<<<dim3(4, NMB), 128, SMEM_DYN>>>(b, out);  // 4 (profiled)

    fixup_kernel<<<512, 256>>>(x, b, out);                      // 5
}